// round 15
// baseline (speedup 1.0000x reference)
#include <cuda_runtime.h>
#include <cuda_fp16.h>
#include <stdint.h>

#define TT 64
#define CC 128
#define HH 64
#define SCALE_Q 0.08838834764831844f   // 128^-0.5

// ---------------- smem layout (byte offsets), NO aliasing ----------------
// XH [128 rows x 136 halves] @0 (34816 B)
// arena @34816: arr 0=Q 1=K 2=V, each [64 x 72] fp16 per batch (9216 B), 2 batches
#define AR(arr, b) (34816 + (arr) * 18432 + (b) * 9216)
#define SMEM_BYTES 90112
#define LDX 136

// ---------------- helpers ----------------
__device__ __forceinline__ uint32_t h2pack(float v0, float v1) {
    __half2 h = __floats2half2_rn(v0, v1);
    return *(uint32_t*)&h;
}
__device__ __forceinline__ void mma16816(float* c,
                                         uint32_t a0, uint32_t a1, uint32_t a2, uint32_t a3,
                                         uint32_t b0, uint32_t b1) {
    asm("mma.sync.aligned.m16n8k16.row.col.f32.f16.f16.f32 "
        "{%0,%1,%2,%3}, {%4,%5,%6,%7}, {%8,%9}, {%0,%1,%2,%3};"
        : "+f"(c[0]), "+f"(c[1]), "+f"(c[2]), "+f"(c[3])
        : "r"(a0), "r"(a1), "r"(a2), "r"(a3), "r"(b0), "r"(b1));
}
__device__ __forceinline__ void ldsm4(uint32_t addr, uint32_t& r0, uint32_t& r1,
                                      uint32_t& r2, uint32_t& r3) {
    asm("ldmatrix.sync.aligned.m8n8.x4.shared.b16 {%0,%1,%2,%3}, [%4];"
        : "=r"(r0), "=r"(r1), "=r"(r2), "=r"(r3) : "r"(addr) : "memory");
}
__device__ __forceinline__ void ldsm4t(uint32_t addr, uint32_t& r0, uint32_t& r1,
                                       uint32_t& r2, uint32_t& r3) {
    asm("ldmatrix.sync.aligned.m8n8.x4.trans.shared.b16 {%0,%1,%2,%3}, [%4];"
        : "=r"(r0), "=r"(r1), "=r"(r2), "=r"(r3) : "r"(addr) : "memory");
}

// ---------------- phases 2+3 statically specialized on row-block WQ ----------
template <int WQ>
__device__ __forceinline__ void phase23(char* sm, uint32_t smb, int bb2, int b0,
                                        int lane, int qk, int lr,
                                        int lmRow, int lmCol, int bfLane, int vfLane,
                                        float* __restrict__ out) {
    constexpr int NT = 2 * (WQ + 1);     // live s2 tiles
    const int mrow = WQ * 16;
    const int rowA = mrow + lr, rowB = rowA + 8;

    float s2[NT][4];
    #pragma unroll
    for (int n = 0; n < NT; n++)
        #pragma unroll
        for (int e = 0; e < 4; e++) s2[n][e] = 0.f;

    const uint32_t qlmBase = smb + (uint32_t)(AR(0, bb2) + mrow * 144 + lmRow * 144 + lmCol);
    const uint32_t kfBase  = smb + (uint32_t)(AR(1, bb2) + bfLane);

    // hoist all Q fragments (k-dim = head dim: all 4 needed)
    uint32_t qf[4][4];
    #pragma unroll
    for (int kt = 0; kt < 4; ++kt)
        ldsm4(qlmBase + (uint32_t)(kt * 32), qf[kt][0], qf[kt][1], qf[kt][2], qf[kt][3]);

    #pragma unroll
    for (int ntp = 0; ntp <= WQ; ++ntp) {
        #pragma unroll
        for (int kt = 0; kt < 4; ++kt) {
            uint32_t b00, b01, b10, b11;
            ldsm4(kfBase + (uint32_t)(ntp * 2304 + kt * 32), b00, b01, b10, b11);
            mma16816(s2[2 * ntp],     qf[kt][0], qf[kt][1], qf[kt][2], qf[kt][3], b00, b01);
            mma16816(s2[2 * ntp + 1], qf[kt][0], qf[kt][1], qf[kt][2], qf[kt][3], b10, b11);
        }
    }

    // ---- causal softmax in registers (live tiles only) ----
    {
        float mA = -1e30f, mB = -1e30f;
        #pragma unroll
        for (int nt = 0; nt < NT; ++nt) {
            int c0 = nt * 8 + qk * 2;
            s2[nt][0] = (c0     <= rowA) ? s2[nt][0] : -1e30f;
            s2[nt][1] = (c0 + 1 <= rowA) ? s2[nt][1] : -1e30f;
            s2[nt][2] = (c0     <= rowB) ? s2[nt][2] : -1e30f;
            s2[nt][3] = (c0 + 1 <= rowB) ? s2[nt][3] : -1e30f;
            mA = fmaxf(mA, fmaxf(s2[nt][0], s2[nt][1]));
            mB = fmaxf(mB, fmaxf(s2[nt][2], s2[nt][3]));
        }
        mA = fmaxf(mA, __shfl_xor_sync(0xffffffffu, mA, 1));
        mA = fmaxf(mA, __shfl_xor_sync(0xffffffffu, mA, 2));
        mB = fmaxf(mB, __shfl_xor_sync(0xffffffffu, mB, 1));
        mB = fmaxf(mB, __shfl_xor_sync(0xffffffffu, mB, 2));
        float sA = 0.f, sB = 0.f;
        #pragma unroll
        for (int nt = 0; nt < NT; ++nt) {
            int c0 = nt * 8 + qk * 2;
            float e0 = (c0     <= rowA) ? __expf(s2[nt][0] - mA) : 0.f;
            float e1 = (c0 + 1 <= rowA) ? __expf(s2[nt][1] - mA) : 0.f;
            float e2 = (c0     <= rowB) ? __expf(s2[nt][2] - mB) : 0.f;
            float e3 = (c0 + 1 <= rowB) ? __expf(s2[nt][3] - mB) : 0.f;
            s2[nt][0] = e0; s2[nt][1] = e1; s2[nt][2] = e2; s2[nt][3] = e3;
            sA += e0 + e1;  sB += e2 + e3;
        }
        sA += __shfl_xor_sync(0xffffffffu, sA, 1);
        sA += __shfl_xor_sync(0xffffffffu, sA, 2);
        sB += __shfl_xor_sync(0xffffffffu, sB, 1);
        sB += __shfl_xor_sync(0xffffffffu, sB, 2);
        float iA = __frcp_rn(sA), iB = __frcp_rn(sB);
        #pragma unroll
        for (int nt = 0; nt < NT; ++nt) {
            s2[nt][0] *= iA; s2[nt][1] *= iA;
            s2[nt][2] *= iB; s2[nt][3] *= iB;
        }
    }

    // ---- Phase 3: O = P @ V (live kt only, V via ldmatrix.trans) ----
    const uint32_t vfBase = smb + (uint32_t)(AR(2, bb2) + vfLane);
    float o[8][4];
    #pragma unroll
    for (int n = 0; n < 8; n++)
        #pragma unroll
        for (int e = 0; e < 4; e++) o[n][e] = 0.f;

    #pragma unroll
    for (int kt = 0; kt <= WQ; ++kt) {
        uint32_t ah0 = h2pack(s2[2 * kt][0],     s2[2 * kt][1]);
        uint32_t ah1 = h2pack(s2[2 * kt][2],     s2[2 * kt][3]);
        uint32_t ah2 = h2pack(s2[2 * kt + 1][0], s2[2 * kt + 1][1]);
        uint32_t ah3 = h2pack(s2[2 * kt + 1][2], s2[2 * kt + 1][3]);
        #pragma unroll
        for (int ntp = 0; ntp < 4; ++ntp) {
            uint32_t b00, b01, b10, b11;
            ldsm4t(vfBase + (uint32_t)(kt * 2304 + ntp * 32), b00, b01, b10, b11);
            mma16816(o[2 * ntp],     ah0, ah1, ah2, ah3, b00, b01);
            mma16816(o[2 * ntp + 1], ah0, ah1, ah2, ah3, b10, b11);
        }
    }

    // ---- store O ----
    float* ob = out + ((size_t)(b0 + bb2) * TT) * HH;
    #pragma unroll
    for (int nt = 0; nt < 8; ++nt) {
        int c0 = nt * 8 + qk * 2;
        *(float2*)&ob[rowA * HH + c0] = make_float2(o[nt][0], o[nt][1]);
        *(float2*)&ob[rowB * HH + c0] = make_float2(o[nt][2], o[nt][3]);
    }
}

// ---------------- main kernel ----------------
__global__ void __launch_bounds__(256, 2)
DiqqetBashi_hmma12_kernel(const float* __restrict__ x,
                          const float* __restrict__ Wq,
                          const float* __restrict__ Wk,
                          const float* __restrict__ Wv,
                          float* __restrict__ out) {
    extern __shared__ char sm[];
    const int tid  = threadIdx.x;
    const int wid  = tid >> 5;
    const int lane = tid & 31;
    const int qk   = lane & 3;
    const int lr   = lane >> 2;
    const int b0   = blockIdx.x * 2;

    const uint32_t smb = (uint32_t)__cvta_generic_to_shared(sm);
    const int lmRow  = (lane & 7) + ((lane >> 3) & 1) * 8;
    const int lmCol  = (lane >> 4) * 16;
    const int bfLane = ((lane >> 4) * 8 + (lane & 7)) * 144 + ((lane >> 3) & 1) * 16;
    const int vfLane = ((((lane >> 3) & 1) * 8) + (lane & 7)) * 144 + (lane >> 4) * 16;

    // ---- build W B-fragments in-register directly from global W ----
    // (identical arithmetic to the old prep kernel; L2-hot after first wave;
    //  LDG latency overlaps the X staging burst below)
    uint2 Bw[3][8];
    #pragma unroll
    for (int j = 0; j < 3; ++j) {
        int nbase = wid * 24 + j * 8;
        int g = nbase >> 6;                  // 0=Wq 1=Wk 2=Wv
        int h = (nbase & 63) + lr;
        const float* Wg = (g == 0) ? Wq : (g == 1) ? Wk : Wv;
        float s = (g == 0) ? SCALE_Q : 1.0f;
        #pragma unroll
        for (int kt = 0; kt < 8; ++kt) {
            int k0 = kt * 16 + qk * 2;
            float w0 = Wg[(k0    ) * HH + h] * s;
            float w1 = Wg[(k0 + 1) * HH + h] * s;
            float w2 = Wg[(k0 + 8) * HH + h] * s;
            float w3 = Wg[(k0 + 9) * HH + h] * s;
            Bw[j][kt] = make_uint2(h2pack(w0, w1), h2pack(w2, w3));
        }
    }

    uint16_t* XH = (uint16_t*)sm;

    // ---- stage X (2 batches = 128 rows x 128 cols f32) -> single fp16 ----
    {
        const float4* x4 = (const float4*)(x + (size_t)b0 * TT * CC);
        #pragma unroll
        for (int it = 0; it < 16; ++it) {
            int idx = tid + it * 256;
            int r = idx >> 5, c0 = (idx & 31) << 2;
            float4 v = x4[idx];
            uint32_t h01 = h2pack(v.x, v.y);
            uint32_t h23 = h2pack(v.z, v.w);
            *(unsigned long long*)&XH[r * LDX + c0] =
                (unsigned long long)h01 | ((unsigned long long)h23 << 32);
        }
    }
    __syncthreads();

    // ================= Phase 1: QKV[128,192] = X[128,128] @ W ================
    const uint32_t xlmBase = smb + (uint32_t)(lmRow * 272 + lmCol);
    const int colb0 = wid * 24;

    #pragma unroll
    for (int mp = 0; mp < 4; ++mp) {
        float a0v[4] = {0.f,0.f,0.f,0.f}, a1v[4] = {0.f,0.f,0.f,0.f}, a2v[4] = {0.f,0.f,0.f,0.f};
        float c0v[4] = {0.f,0.f,0.f,0.f}, c1v[4] = {0.f,0.f,0.f,0.f}, c2v[4] = {0.f,0.f,0.f,0.f};
        #pragma unroll
        for (int kt = 0; kt < 8; ++kt) {
            uint32_t f0, f1, f2, f3, g0, g1, g2, g3;
            ldsm4(xlmBase + (uint32_t)((2 * mp)     * 16 * 272 + kt * 32), f0, f1, f2, f3);
            ldsm4(xlmBase + (uint32_t)((2 * mp + 1) * 16 * 272 + kt * 32), g0, g1, g2, g3);
            mma16816(a0v, f0, f1, f2, f3, Bw[0][kt].x, Bw[0][kt].y);
            mma16816(c0v, g0, g1, g2, g3, Bw[0][kt].x, Bw[0][kt].y);
            mma16816(a1v, f0, f1, f2, f3, Bw[1][kt].x, Bw[1][kt].y);
            mma16816(c1v, g0, g1, g2, g3, Bw[1][kt].x, Bw[1][kt].y);
            mma16816(a2v, f0, f1, f2, f3, Bw[2][kt].x, Bw[2][kt].y);
            mma16816(c2v, g0, g1, g2, g3, Bw[2][kt].x, Bw[2][kt].y);
        }
        #pragma unroll
        for (int half = 0; half < 2; ++half) {
            int m = 2 * mp + half;
            int rA = m * 16 + lr;
            int rB = rA + 8;
            int b_ = rA >> 6;
            int tA = rA & 63, tB = rB & 63;
            float* v0 = half ? c0v : a0v;
            float* v1 = half ? c1v : a1v;
            float* v2 = half ? c2v : a2v;
            #pragma unroll
            for (int j = 0; j < 3; ++j) {
                int colbase = colb0 + j * 8;
                int rg = colbase >> 6;          // 0=Q 1=K 2=V
                int ci = ((colbase & 63) >> 1) + qk;
                float* a = (j == 0) ? v0 : (j == 1) ? v1 : v2;
                uint32_t* D = (uint32_t*)(sm + AR(rg, b_));
                D[tA * 36 + ci] = h2pack(a[0], a[1]);
                D[tB * 36 + ci] = h2pack(a[2], a[3]);
            }
        }
    }
    __syncthreads();

    // ================= Phases 2+3: static dispatch on row-block =============
    const int bb2 = wid >> 2;
    switch (wid & 3) {
        case 0: phase23<0>(sm, smb, bb2, b0, lane, qk, lr, lmRow, lmCol, bfLane, vfLane, out); break;
        case 1: phase23<1>(sm, smb, bb2, b0, lane, qk, lr, lmRow, lmCol, bfLane, vfLane, out); break;
        case 2: phase23<2>(sm, smb, bb2, b0, lane, qk, lr, lmRow, lmCol, bfLane, vfLane, out); break;
        default: phase23<3>(sm, smb, bb2, b0, lane, qk, lr, lmRow, lmCol, bfLane, vfLane, out); break;
    }
}

extern "C" void kernel_launch(void* const* d_in, const int* in_sizes, int n_in,
                              void* d_out, int out_size) {
    const float* x  = (const float*)d_in[0];
    const float* Wq = (const float*)d_in[1];
    const float* Wk = (const float*)d_in[2];
    const float* Wv = (const float*)d_in[3];
    float* out = (float*)d_out;

    int B = in_sizes[0] / (TT * CC);

    cudaFuncSetAttribute(DiqqetBashi_hmma12_kernel,
                         cudaFuncAttributeMaxDynamicSharedMemorySize, SMEM_BYTES);
    DiqqetBashi_hmma12_kernel<<<B / 2, 256, SMEM_BYTES>>>(x, Wq, Wk, Wv, out);
}

// round 16
// speedup vs baseline: 1.2067x; 1.2067x over previous
#include <cuda_runtime.h>
#include <cuda_fp16.h>
#include <stdint.h>

#define TT 64
#define CC 128
#define HH 64
#define SCALE_Q 0.08838834764831844f   // 128^-0.5

// W single-fp16 fragment-ordered: [nt(24)][kt(8)][lane(32)] -> {b0,b1}
__device__ uint2 WFRAG[6144];

// ---------------- smem layout (byte offsets), NO aliasing ----------------
// XH [128 rows x 136 halves] @0 (34816 B)
// arena @34816: arr 0=Q 1=K 2=V, each [64 x 72] fp16 per batch (9216 B), 2 batches
#define AR(arr, b) (34816 + (arr) * 18432 + (b) * 9216)
#define SMEM_BYTES 90112
#define LDX 136

// ---------------- helpers ----------------
__device__ __forceinline__ uint32_t h2pack(float v0, float v1) {
    __half2 h = __floats2half2_rn(v0, v1);
    return *(uint32_t*)&h;
}
__device__ __forceinline__ void mma16816(float* c,
                                         uint32_t a0, uint32_t a1, uint32_t a2, uint32_t a3,
                                         uint32_t b0, uint32_t b1) {
    asm("mma.sync.aligned.m16n8k16.row.col.f32.f16.f16.f32 "
        "{%0,%1,%2,%3}, {%4,%5,%6,%7}, {%8,%9}, {%0,%1,%2,%3};"
        : "+f"(c[0]), "+f"(c[1]), "+f"(c[2]), "+f"(c[3])
        : "r"(a0), "r"(a1), "r"(a2), "r"(a3), "r"(b0), "r"(b1));
}
__device__ __forceinline__ void ldsm4(uint32_t addr, uint32_t& r0, uint32_t& r1,
                                      uint32_t& r2, uint32_t& r3) {
    asm("ldmatrix.sync.aligned.m8n8.x4.shared.b16 {%0,%1,%2,%3}, [%4];"
        : "=r"(r0), "=r"(r1), "=r"(r2), "=r"(r3) : "r"(addr) : "memory");
}
__device__ __forceinline__ void ldsm4t(uint32_t addr, uint32_t& r0, uint32_t& r1,
                                       uint32_t& r2, uint32_t& r3) {
    asm("ldmatrix.sync.aligned.m8n8.x4.trans.shared.b16 {%0,%1,%2,%3}, [%4];"
        : "=r"(r0), "=r"(r1), "=r"(r2), "=r"(r3) : "r"(addr) : "memory");
}

// ---------------- prep kernel: W -> fragment-ordered fp16 global ----------------
__global__ void prep_w_kernel(const float* __restrict__ Wq,
                              const float* __restrict__ Wk,
                              const float* __restrict__ Wv) {
    int i = blockIdx.x * 256 + threadIdx.x;
    if (i >= 6144) return;
    int lane = i & 31;
    int kt   = (i >> 5) & 7;
    int nt   = i >> 8;
    int qk = lane & 3, lr = lane >> 2;
    int n = nt * 8 + lr;
    int g = n >> 6, h = n & 63;
    const float* Wg = (g == 0) ? Wq : (g == 1) ? Wk : Wv;
    float s = (g == 0) ? SCALE_Q : 1.0f;
    int k0 = kt * 16 + qk * 2;
    float w0 = Wg[(k0    ) * HH + h] * s;
    float w1 = Wg[(k0 + 1) * HH + h] * s;
    float w2 = Wg[(k0 + 8) * HH + h] * s;
    float w3 = Wg[(k0 + 9) * HH + h] * s;
    WFRAG[i] = make_uint2(h2pack(w0, w1), h2pack(w2, w3));
}

// ---------------- phases 2+3 statically specialized on row-block WQ ----------
template <int WQ>
__device__ __forceinline__ void phase23(char* sm, uint32_t smb, int bb2, int b0,
                                        int lane, int qk, int lr,
                                        int lmRow, int lmCol, int bfLane, int vfLane,
                                        float* __restrict__ out) {
    constexpr int NT = 2 * (WQ + 1);     // live s2 tiles
    const int mrow = WQ * 16;
    const int rowA = mrow + lr, rowB = rowA + 8;

    float s2[NT][4];
    #pragma unroll
    for (int n = 0; n < NT; n++)
        #pragma unroll
        for (int e = 0; e < 4; e++) s2[n][e] = 0.f;

    const uint32_t qlmBase = smb + (uint32_t)(AR(0, bb2) + mrow * 144 + lmRow * 144 + lmCol);
    const uint32_t kfBase  = smb + (uint32_t)(AR(1, bb2) + bfLane);

    // hoist all Q fragments (k-dim = head dim: all 4 needed)
    uint32_t qf[4][4];
    #pragma unroll
    for (int kt = 0; kt < 4; ++kt)
        ldsm4(qlmBase + (uint32_t)(kt * 32), qf[kt][0], qf[kt][1], qf[kt][2], qf[kt][3]);

    #pragma unroll
    for (int ntp = 0; ntp <= WQ; ++ntp) {
        #pragma unroll
        for (int kt = 0; kt < 4; ++kt) {
            uint32_t b00, b01, b10, b11;
            ldsm4(kfBase + (uint32_t)(ntp * 2304 + kt * 32), b00, b01, b10, b11);
            mma16816(s2[2 * ntp],     qf[kt][0], qf[kt][1], qf[kt][2], qf[kt][3], b00, b01);
            mma16816(s2[2 * ntp + 1], qf[kt][0], qf[kt][1], qf[kt][2], qf[kt][3], b10, b11);
        }
    }

    // ---- causal softmax in registers (live tiles only) ----
    {
        float mA = -1e30f, mB = -1e30f;
        #pragma unroll
        for (int nt = 0; nt < NT; ++nt) {
            int c0 = nt * 8 + qk * 2;
            s2[nt][0] = (c0     <= rowA) ? s2[nt][0] : -1e30f;
            s2[nt][1] = (c0 + 1 <= rowA) ? s2[nt][1] : -1e30f;
            s2[nt][2] = (c0     <= rowB) ? s2[nt][2] : -1e30f;
            s2[nt][3] = (c0 + 1 <= rowB) ? s2[nt][3] : -1e30f;
            mA = fmaxf(mA, fmaxf(s2[nt][0], s2[nt][1]));
            mB = fmaxf(mB, fmaxf(s2[nt][2], s2[nt][3]));
        }
        mA = fmaxf(mA, __shfl_xor_sync(0xffffffffu, mA, 1));
        mA = fmaxf(mA, __shfl_xor_sync(0xffffffffu, mA, 2));
        mB = fmaxf(mB, __shfl_xor_sync(0xffffffffu, mB, 1));
        mB = fmaxf(mB, __shfl_xor_sync(0xffffffffu, mB, 2));
        float sA = 0.f, sB = 0.f;
        #pragma unroll
        for (int nt = 0; nt < NT; ++nt) {
            int c0 = nt * 8 + qk * 2;
            float e0 = (c0     <= rowA) ? __expf(s2[nt][0] - mA) : 0.f;
            float e1 = (c0 + 1 <= rowA) ? __expf(s2[nt][1] - mA) : 0.f;
            float e2 = (c0     <= rowB) ? __expf(s2[nt][2] - mB) : 0.f;
            float e3 = (c0 + 1 <= rowB) ? __expf(s2[nt][3] - mB) : 0.f;
            s2[nt][0] = e0; s2[nt][1] = e1; s2[nt][2] = e2; s2[nt][3] = e3;
            sA += e0 + e1;  sB += e2 + e3;
        }
        sA += __shfl_xor_sync(0xffffffffu, sA, 1);
        sA += __shfl_xor_sync(0xffffffffu, sA, 2);
        sB += __shfl_xor_sync(0xffffffffu, sB, 1);
        sB += __shfl_xor_sync(0xffffffffu, sB, 2);
        float iA = __frcp_rn(sA), iB = __frcp_rn(sB);
        #pragma unroll
        for (int nt = 0; nt < NT; ++nt) {
            s2[nt][0] *= iA; s2[nt][1] *= iA;
            s2[nt][2] *= iB; s2[nt][3] *= iB;
        }
    }

    // ---- Phase 3: O = P @ V (live kt only, V via ldmatrix.trans) ----
    const uint32_t vfBase = smb + (uint32_t)(AR(2, bb2) + vfLane);
    float o[8][4];
    #pragma unroll
    for (int n = 0; n < 8; n++)
        #pragma unroll
        for (int e = 0; e < 4; e++) o[n][e] = 0.f;

    #pragma unroll
    for (int kt = 0; kt <= WQ; ++kt) {
        uint32_t ah0 = h2pack(s2[2 * kt][0],     s2[2 * kt][1]);
        uint32_t ah1 = h2pack(s2[2 * kt][2],     s2[2 * kt][3]);
        uint32_t ah2 = h2pack(s2[2 * kt + 1][0], s2[2 * kt + 1][1]);
        uint32_t ah3 = h2pack(s2[2 * kt + 1][2], s2[2 * kt + 1][3]);
        #pragma unroll
        for (int ntp = 0; ntp < 4; ++ntp) {
            uint32_t b00, b01, b10, b11;
            ldsm4t(vfBase + (uint32_t)(kt * 2304 + ntp * 32), b00, b01, b10, b11);
            mma16816(o[2 * ntp],     ah0, ah1, ah2, ah3, b00, b01);
            mma16816(o[2 * ntp + 1], ah0, ah1, ah2, ah3, b10, b11);
        }
    }

    // ---- store O ----
    float* ob = out + ((size_t)(b0 + bb2) * TT) * HH;
    #pragma unroll
    for (int nt = 0; nt < 8; ++nt) {
        int c0 = nt * 8 + qk * 2;
        *(float2*)&ob[rowA * HH + c0] = make_float2(o[nt][0], o[nt][1]);
        *(float2*)&ob[rowB * HH + c0] = make_float2(o[nt][2], o[nt][3]);
    }
}

// ---------------- main kernel ----------------
__global__ void __launch_bounds__(256, 2)
DiqqetBashi_hmma13_kernel(const float* __restrict__ x,
                          float* __restrict__ out) {
    extern __shared__ char sm[];
    const int tid  = threadIdx.x;
    const int wid  = tid >> 5;
    const int lane = tid & 31;
    const int qk   = lane & 3;
    const int lr   = lane >> 2;
    const int b0   = blockIdx.x * 2;

    const uint32_t smb = (uint32_t)__cvta_generic_to_shared(sm);
    const int lmRow  = (lane & 7) + ((lane >> 3) & 1) * 8;
    const int lmCol  = (lane >> 4) * 16;
    const int bfLane = ((lane >> 4) * 8 + (lane & 7)) * 144 + ((lane >> 3) & 1) * 16;
    const int vfLane = ((((lane >> 3) & 1) * 8) + (lane & 7)) * 144 + (lane >> 4) * 16;

    uint16_t* XH = (uint16_t*)sm;
    const float4* x4 = (const float4*)(x + (size_t)b0 * TT * CC);

    // ---- stage X batch 0: issue 8 LDG.128 back-to-back (MLP 8) ----
    float4 xv[8];
    #pragma unroll
    for (int it = 0; it < 8; ++it) xv[it] = x4[tid + it * 256];

    // ---- Bw loads slot under the X DRAM latency (needed only after barrier) ----
    uint2 Bw[3][8];
    #pragma unroll
    for (int j = 0; j < 3; ++j)
        #pragma unroll
        for (int kt = 0; kt < 8; ++kt)
            Bw[j][kt] = WFRAG[((wid * 3 + j) * 8 + kt) * 32 + lane];

    // ---- drain batch 0, then batch 1 ----
    #pragma unroll
    for (int it = 0; it < 8; ++it) {
        int idx = tid + it * 256;
        int r = idx >> 5, c0 = (idx & 31) << 2;
        uint32_t h01 = h2pack(xv[it].x, xv[it].y);
        uint32_t h23 = h2pack(xv[it].z, xv[it].w);
        *(unsigned long long*)&XH[r * LDX + c0] =
            (unsigned long long)h01 | ((unsigned long long)h23 << 32);
    }
    #pragma unroll
    for (int it = 0; it < 8; ++it) xv[it] = x4[tid + (it + 8) * 256];
    #pragma unroll
    for (int it = 0; it < 8; ++it) {
        int idx = tid + (it + 8) * 256;
        int r = idx >> 5, c0 = (idx & 31) << 2;
        uint32_t h01 = h2pack(xv[it].x, xv[it].y);
        uint32_t h23 = h2pack(xv[it].z, xv[it].w);
        *(unsigned long long*)&XH[r * LDX + c0] =
            (unsigned long long)h01 | ((unsigned long long)h23 << 32);
    }
    __syncthreads();

    // ================= Phase 1: QKV[128,192] = X[128,128] @ W ================
    const uint32_t xlmBase = smb + (uint32_t)(lmRow * 272 + lmCol);
    const int colb0 = wid * 24;

    #pragma unroll
    for (int mp = 0; mp < 4; ++mp) {
        float a0v[4] = {0.f,0.f,0.f,0.f}, a1v[4] = {0.f,0.f,0.f,0.f}, a2v[4] = {0.f,0.f,0.f,0.f};
        float c0v[4] = {0.f,0.f,0.f,0.f}, c1v[4] = {0.f,0.f,0.f,0.f}, c2v[4] = {0.f,0.f,0.f,0.f};
        #pragma unroll
        for (int kt = 0; kt < 8; ++kt) {
            uint32_t f0, f1, f2, f3, g0, g1, g2, g3;
            ldsm4(xlmBase + (uint32_t)((2 * mp)     * 16 * 272 + kt * 32), f0, f1, f2, f3);
            ldsm4(xlmBase + (uint32_t)((2 * mp + 1) * 16 * 272 + kt * 32), g0, g1, g2, g3);
            mma16816(a0v, f0, f1, f2, f3, Bw[0][kt].x, Bw[0][kt].y);
            mma16816(c0v, g0, g1, g2, g3, Bw[0][kt].x, Bw[0][kt].y);
            mma16816(a1v, f0, f1, f2, f3, Bw[1][kt].x, Bw[1][kt].y);
            mma16816(c1v, g0, g1, g2, g3, Bw[1][kt].x, Bw[1][kt].y);
            mma16816(a2v, f0, f1, f2, f3, Bw[2][kt].x, Bw[2][kt].y);
            mma16816(c2v, g0, g1, g2, g3, Bw[2][kt].x, Bw[2][kt].y);
        }
        #pragma unroll
        for (int half = 0; half < 2; ++half) {
            int m = 2 * mp + half;
            int rA = m * 16 + lr;
            int rB = rA + 8;
            int b_ = rA >> 6;
            int tA = rA & 63, tB = rB & 63;
            float* v0 = half ? c0v : a0v;
            float* v1 = half ? c1v : a1v;
            float* v2 = half ? c2v : a2v;
            #pragma unroll
            for (int j = 0; j < 3; ++j) {
                int colbase = colb0 + j * 8;
                int rg = colbase >> 6;          // 0=Q 1=K 2=V
                int ci = ((colbase & 63) >> 1) + qk;
                float* a = (j == 0) ? v0 : (j == 1) ? v1 : v2;
                uint32_t* D = (uint32_t*)(sm + AR(rg, b_));
                D[tA * 36 + ci] = h2pack(a[0], a[1]);
                D[tB * 36 + ci] = h2pack(a[2], a[3]);
            }
        }
    }
    __syncthreads();

    // ================= Phases 2+3: static dispatch on row-block =============
    const int bb2 = wid >> 2;
    switch (wid & 3) {
        case 0: phase23<0>(sm, smb, bb2, b0, lane, qk, lr, lmRow, lmCol, bfLane, vfLane, out); break;
        case 1: phase23<1>(sm, smb, bb2, b0, lane, qk, lr, lmRow, lmCol, bfLane, vfLane, out); break;
        case 2: phase23<2>(sm, smb, bb2, b0, lane, qk, lr, lmRow, lmCol, bfLane, vfLane, out); break;
        default: phase23<3>(sm, smb, bb2, b0, lane, qk, lr, lmRow, lmCol, bfLane, vfLane, out); break;
    }
}

extern "C" void kernel_launch(void* const* d_in, const int* in_sizes, int n_in,
                              void* d_out, int out_size) {
    const float* x  = (const float*)d_in[0];
    const float* Wq = (const float*)d_in[1];
    const float* Wk = (const float*)d_in[2];
    const float* Wv = (const float*)d_in[3];
    float* out = (float*)d_out;

    int B = in_sizes[0] / (TT * CC);

    prep_w_kernel<<<24, 256>>>(Wq, Wk, Wv);

    cudaFuncSetAttribute(DiqqetBashi_hmma13_kernel,
                         cudaFuncAttributeMaxDynamicSharedMemorySize, SMEM_BYTES);
    DiqqetBashi_hmma13_kernel<<<B / 2, 256, SMEM_BYTES>>>(x, out);
}

// round 17
// speedup vs baseline: 1.2167x; 1.0082x over previous
#include <cuda_runtime.h>
#include <cuda_fp16.h>
#include <stdint.h>

#define TT 64
#define CC 128
#define HH 64
#define SCALE_Q 0.08838834764831844f   // 128^-0.5

// W single-fp16 fragment-ordered: [nt(24)][kt(8)][lane(32)] -> {b0,b1}
__device__ uint2 WFRAG[6144];

// ---------------- smem layout (byte offsets), NO aliasing ----------------
// XH [128 rows x 136 halves] @0 (34816 B)
// arena @34816: arr 0=Q 1=K 2=V, each [64 x 72] fp16 per batch (9216 B), 2 batches
#define AR(arr, b) (34816 + (arr) * 18432 + (b) * 9216)
#define SMEM_BYTES 90112
#define LDX 136

// ---------------- helpers ----------------
__device__ __forceinline__ uint32_t h2pack(float v0, float v1) {
    __half2 h = __floats2half2_rn(v0, v1);
    return *(uint32_t*)&h;
}
__device__ __forceinline__ void mma16816(float* c,
                                         uint32_t a0, uint32_t a1, uint32_t a2, uint32_t a3,
                                         uint32_t b0, uint32_t b1) {
    asm("mma.sync.aligned.m16n8k16.row.col.f32.f16.f16.f32 "
        "{%0,%1,%2,%3}, {%4,%5,%6,%7}, {%8,%9}, {%0,%1,%2,%3};"
        : "+f"(c[0]), "+f"(c[1]), "+f"(c[2]), "+f"(c[3])
        : "r"(a0), "r"(a1), "r"(a2), "r"(a3), "r"(b0), "r"(b1));
}
__device__ __forceinline__ void ldsm4(uint32_t addr, uint32_t& r0, uint32_t& r1,
                                      uint32_t& r2, uint32_t& r3) {
    asm("ldmatrix.sync.aligned.m8n8.x4.shared.b16 {%0,%1,%2,%3}, [%4];"
        : "=r"(r0), "=r"(r1), "=r"(r2), "=r"(r3) : "r"(addr) : "memory");
}
__device__ __forceinline__ void ldsm4t(uint32_t addr, uint32_t& r0, uint32_t& r1,
                                       uint32_t& r2, uint32_t& r3) {
    asm("ldmatrix.sync.aligned.m8n8.x4.trans.shared.b16 {%0,%1,%2,%3}, [%4];"
        : "=r"(r0), "=r"(r1), "=r"(r2), "=r"(r3) : "r"(addr) : "memory");
}

// ---------------- prep kernel: W -> fragment-ordered fp16 global ----------------
__global__ void prep_w_kernel(const float* __restrict__ Wq,
                              const float* __restrict__ Wk,
                              const float* __restrict__ Wv) {
    int i = blockIdx.x * 256 + threadIdx.x;
    if (i >= 6144) return;
    int lane = i & 31;
    int kt   = (i >> 5) & 7;
    int nt   = i >> 8;
    int qk = lane & 3, lr = lane >> 2;
    int n = nt * 8 + lr;
    int g = n >> 6, h = n & 63;
    const float* Wg = (g == 0) ? Wq : (g == 1) ? Wk : Wv;
    float s = (g == 0) ? SCALE_Q : 1.0f;
    int k0 = kt * 16 + qk * 2;
    float w0 = Wg[(k0    ) * HH + h] * s;
    float w1 = Wg[(k0 + 1) * HH + h] * s;
    float w2 = Wg[(k0 + 8) * HH + h] * s;
    float w3 = Wg[(k0 + 9) * HH + h] * s;
    WFRAG[i] = make_uint2(h2pack(w0, w1), h2pack(w2, w3));
}

// ---------------- phases 2+3 statically specialized on row-block WQ ----------
template <int WQ>
__device__ __forceinline__ void phase23(char* sm, uint32_t smb, int bb2, int b0,
                                        int lane, int qk, int lr,
                                        int lmRow, int lmCol, int bfLane, int vfLane,
                                        float* __restrict__ out) {
    constexpr int NT = 2 * (WQ + 1);     // live s2 tiles
    constexpr int NI = 4 * (WQ + 1);     // phase-2 flattened iterations
    const int mrow = WQ * 16;
    const int rowA = mrow + lr, rowB = rowA + 8;

    float s2[NT][4];
    #pragma unroll
    for (int n = 0; n < NT; n++)
        #pragma unroll
        for (int e = 0; e < 4; e++) s2[n][e] = 0.f;

    const uint32_t qlmBase = smb + (uint32_t)(AR(0, bb2) + mrow * 144 + lmRow * 144 + lmCol);
    const uint32_t kfBase  = smb + (uint32_t)(AR(1, bb2) + bfLane);
    const uint32_t vfBase  = smb + (uint32_t)(AR(2, bb2) + vfLane);

    // hoist all Q fragments (k-dim = head dim: all 4 needed)
    uint32_t qf[4][4];
    #pragma unroll
    for (int kt = 0; kt < 4; ++kt)
        ldsm4(qlmBase + (uint32_t)(kt * 32), qf[kt][0], qf[kt][1], qf[kt][2], qf[kt][3]);

    // ---- phase 2: flattened + double-buffered K fragments ----
    {
        uint32_t kb[4], kn[4];
        ldsm4(kfBase, kb[0], kb[1], kb[2], kb[3]);
        #pragma unroll
        for (int i = 0; i < NI; ++i) {
            if (i + 1 < NI) {
                int ntp1 = (i + 1) >> 2, kt1 = (i + 1) & 3;
                ldsm4(kfBase + (uint32_t)(ntp1 * 2304 + kt1 * 32),
                      kn[0], kn[1], kn[2], kn[3]);
            }
            int ntp = i >> 2, kt = i & 3;
            mma16816(s2[2 * ntp],     qf[kt][0], qf[kt][1], qf[kt][2], qf[kt][3], kb[0], kb[1]);
            mma16816(s2[2 * ntp + 1], qf[kt][0], qf[kt][1], qf[kt][2], qf[kt][3], kb[2], kb[3]);
            #pragma unroll
            for (int e = 0; e < 4; ++e) kb[e] = kn[e];
        }
    }

    // ---- prefetch V fragments for kt=0 (independent of softmax) ----
    uint32_t vc[16];
    #pragma unroll
    for (int ntp = 0; ntp < 4; ++ntp)
        ldsm4t(vfBase + (uint32_t)(ntp * 32),
               vc[4 * ntp], vc[4 * ntp + 1], vc[4 * ntp + 2], vc[4 * ntp + 3]);

    // ---- causal softmax in registers (live tiles only) ----
    {
        float mA = -1e30f, mB = -1e30f;
        #pragma unroll
        for (int nt = 0; nt < NT; ++nt) {
            int c0 = nt * 8 + qk * 2;
            s2[nt][0] = (c0     <= rowA) ? s2[nt][0] : -1e30f;
            s2[nt][1] = (c0 + 1 <= rowA) ? s2[nt][1] : -1e30f;
            s2[nt][2] = (c0     <= rowB) ? s2[nt][2] : -1e30f;
            s2[nt][3] = (c0 + 1 <= rowB) ? s2[nt][3] : -1e30f;
            mA = fmaxf(mA, fmaxf(s2[nt][0], s2[nt][1]));
            mB = fmaxf(mB, fmaxf(s2[nt][2], s2[nt][3]));
        }
        mA = fmaxf(mA, __shfl_xor_sync(0xffffffffu, mA, 1));
        mA = fmaxf(mA, __shfl_xor_sync(0xffffffffu, mA, 2));
        mB = fmaxf(mB, __shfl_xor_sync(0xffffffffu, mB, 1));
        mB = fmaxf(mB, __shfl_xor_sync(0xffffffffu, mB, 2));
        float sA = 0.f, sB = 0.f;
        #pragma unroll
        for (int nt = 0; nt < NT; ++nt) {
            int c0 = nt * 8 + qk * 2;
            float e0 = (c0     <= rowA) ? __expf(s2[nt][0] - mA) : 0.f;
            float e1 = (c0 + 1 <= rowA) ? __expf(s2[nt][1] - mA) : 0.f;
            float e2 = (c0     <= rowB) ? __expf(s2[nt][2] - mB) : 0.f;
            float e3 = (c0 + 1 <= rowB) ? __expf(s2[nt][3] - mB) : 0.f;
            s2[nt][0] = e0; s2[nt][1] = e1; s2[nt][2] = e2; s2[nt][3] = e3;
            sA += e0 + e1;  sB += e2 + e3;
        }
        sA += __shfl_xor_sync(0xffffffffu, sA, 1);
        sA += __shfl_xor_sync(0xffffffffu, sA, 2);
        sB += __shfl_xor_sync(0xffffffffu, sB, 1);
        sB += __shfl_xor_sync(0xffffffffu, sB, 2);
        float iA = __frcp_rn(sA), iB = __frcp_rn(sB);
        #pragma unroll
        for (int nt = 0; nt < NT; ++nt) {
            s2[nt][0] *= iA; s2[nt][1] *= iA;
            s2[nt][2] *= iB; s2[nt][3] *= iB;
        }
    }

    // ---- Phase 3: O = P @ V, V double-buffered across kt ----
    float o[8][4];
    #pragma unroll
    for (int n = 0; n < 8; n++)
        #pragma unroll
        for (int e = 0; e < 4; e++) o[n][e] = 0.f;

    #pragma unroll
    for (int kt = 0; kt <= WQ; ++kt) {
        uint32_t vn[16];
        if (kt < WQ) {
            #pragma unroll
            for (int ntp = 0; ntp < 4; ++ntp)
                ldsm4t(vfBase + (uint32_t)((kt + 1) * 2304 + ntp * 32),
                       vn[4 * ntp], vn[4 * ntp + 1], vn[4 * ntp + 2], vn[4 * ntp + 3]);
        }
        uint32_t ah0 = h2pack(s2[2 * kt][0],     s2[2 * kt][1]);
        uint32_t ah1 = h2pack(s2[2 * kt][2],     s2[2 * kt][3]);
        uint32_t ah2 = h2pack(s2[2 * kt + 1][0], s2[2 * kt + 1][1]);
        uint32_t ah3 = h2pack(s2[2 * kt + 1][2], s2[2 * kt + 1][3]);
        #pragma unroll
        for (int ntp = 0; ntp < 4; ++ntp) {
            mma16816(o[2 * ntp],     ah0, ah1, ah2, ah3, vc[4 * ntp],     vc[4 * ntp + 1]);
            mma16816(o[2 * ntp + 1], ah0, ah1, ah2, ah3, vc[4 * ntp + 2], vc[4 * ntp + 3]);
        }
        if (kt < WQ) {
            #pragma unroll
            for (int e = 0; e < 16; ++e) vc[e] = vn[e];
        }
    }

    // ---- store O ----
    float* ob = out + ((size_t)(b0 + bb2) * TT) * HH;
    #pragma unroll
    for (int nt = 0; nt < 8; ++nt) {
        int c0 = nt * 8 + qk * 2;
        *(float2*)&ob[rowA * HH + c0] = make_float2(o[nt][0], o[nt][1]);
        *(float2*)&ob[rowB * HH + c0] = make_float2(o[nt][2], o[nt][3]);
    }
}

// ---------------- main kernel ----------------
__global__ void __launch_bounds__(256, 2)
DiqqetBashi_hmma14_kernel(const float* __restrict__ x,
                          float* __restrict__ out) {
    extern __shared__ char sm[];
    const int tid  = threadIdx.x;
    const int wid  = tid >> 5;
    const int lane = tid & 31;
    const int qk   = lane & 3;
    const int lr   = lane >> 2;
    const int b0   = blockIdx.x * 2;

    const uint32_t smb = (uint32_t)__cvta_generic_to_shared(sm);
    const int lmRow  = (lane & 7) + ((lane >> 3) & 1) * 8;
    const int lmCol  = (lane >> 4) * 16;
    const int bfLane = ((lane >> 4) * 8 + (lane & 7)) * 144 + ((lane >> 3) & 1) * 16;
    const int vfLane = ((((lane >> 3) & 1) * 8) + (lane & 7)) * 144 + (lane >> 4) * 16;

    // ---- hoist all W B-fragments (latency overlaps X staging) ----
    uint2 Bw[3][8];
    #pragma unroll
    for (int j = 0; j < 3; ++j)
        #pragma unroll
        for (int kt = 0; kt < 8; ++kt)
            Bw[j][kt] = WFRAG[((wid * 3 + j) * 8 + kt) * 32 + lane];

    uint16_t* XH = (uint16_t*)sm;

    // ---- stage X (2 batches = 128 rows x 128 cols f32) -> single fp16 ----
    {
        const float4* x4 = (const float4*)(x + (size_t)b0 * TT * CC);
        #pragma unroll
        for (int it = 0; it < 16; ++it) {
            int idx = tid + it * 256;
            int r = idx >> 5, c0 = (idx & 31) << 2;
            float4 v = x4[idx];
            uint32_t h01 = h2pack(v.x, v.y);
            uint32_t h23 = h2pack(v.z, v.w);
            *(unsigned long long*)&XH[r * LDX + c0] =
                (unsigned long long)h01 | ((unsigned long long)h23 << 32);
        }
    }
    __syncthreads();

    // ================= Phase 1: QKV[128,192] = X[128,128] @ W ================
    const uint32_t xlmBase = smb + (uint32_t)(lmRow * 272 + lmCol);
    const int colb0 = wid * 24;

    #pragma unroll
    for (int mp = 0; mp < 4; ++mp) {
        float a0v[4] = {0.f,0.f,0.f,0.f}, a1v[4] = {0.f,0.f,0.f,0.f}, a2v[4] = {0.f,0.f,0.f,0.f};
        float c0v[4] = {0.f,0.f,0.f,0.f}, c1v[4] = {0.f,0.f,0.f,0.f}, c2v[4] = {0.f,0.f,0.f,0.f};
        #pragma unroll
        for (int kt = 0; kt < 8; ++kt) {
            uint32_t f0, f1, f2, f3, g0, g1, g2, g3;
            ldsm4(xlmBase + (uint32_t)((2 * mp)     * 16 * 272 + kt * 32), f0, f1, f2, f3);
            ldsm4(xlmBase + (uint32_t)((2 * mp + 1) * 16 * 272 + kt * 32), g0, g1, g2, g3);
            mma16816(a0v, f0, f1, f2, f3, Bw[0][kt].x, Bw[0][kt].y);
            mma16816(c0v, g0, g1, g2, g3, Bw[0][kt].x, Bw[0][kt].y);
            mma16816(a1v, f0, f1, f2, f3, Bw[1][kt].x, Bw[1][kt].y);
            mma16816(c1v, g0, g1, g2, g3, Bw[1][kt].x, Bw[1][kt].y);
            mma16816(a2v, f0, f1, f2, f3, Bw[2][kt].x, Bw[2][kt].y);
            mma16816(c2v, g0, g1, g2, g3, Bw[2][kt].x, Bw[2][kt].y);
        }
        #pragma unroll
        for (int half = 0; half < 2; ++half) {
            int m = 2 * mp + half;
            int rA = m * 16 + lr;
            int rB = rA + 8;
            int b_ = rA >> 6;
            int tA = rA & 63, tB = rB & 63;
            float* v0 = half ? c0v : a0v;
            float* v1 = half ? c1v : a1v;
            float* v2 = half ? c2v : a2v;
            #pragma unroll
            for (int j = 0; j < 3; ++j) {
                int colbase = colb0 + j * 8;
                int rg = colbase >> 6;          // 0=Q 1=K 2=V
                int ci = ((colbase & 63) >> 1) + qk;
                float* a = (j == 0) ? v0 : (j == 1) ? v1 : v2;
                uint32_t* D = (uint32_t*)(sm + AR(rg, b_));
                D[tA * 36 + ci] = h2pack(a[0], a[1]);
                D[tB * 36 + ci] = h2pack(a[2], a[3]);
            }
        }
    }
    __syncthreads();

    // ================= Phases 2+3: static dispatch on row-block =============
    const int bb2 = wid >> 2;
    switch (wid & 3) {
        case 0: phase23<0>(sm, smb, bb2, b0, lane, qk, lr, lmRow, lmCol, bfLane, vfLane, out); break;
        case 1: phase23<1>(sm, smb, bb2, b0, lane, qk, lr, lmRow, lmCol, bfLane, vfLane, out); break;
        case 2: phase23<2>(sm, smb, bb2, b0, lane, qk, lr, lmRow, lmCol, bfLane, vfLane, out); break;
        default: phase23<3>(sm, smb, bb2, b0, lane, qk, lr, lmRow, lmCol, bfLane, vfLane, out); break;
    }
}

extern "C" void kernel_launch(void* const* d_in, const int* in_sizes, int n_in,
                              void* d_out, int out_size) {
    const float* x  = (const float*)d_in[0];
    const float* Wq = (const float*)d_in[1];
    const float* Wk = (const float*)d_in[2];
    const float* Wv = (const float*)d_in[3];
    float* out = (float*)d_out;

    int B = in_sizes[0] / (TT * CC);

    prep_w_kernel<<<24, 256>>>(Wq, Wk, Wv);

    cudaFuncSetAttribute(DiqqetBashi_hmma14_kernel,
                         cudaFuncAttributeMaxDynamicSharedMemorySize, SMEM_BYTES);
    DiqqetBashi_hmma14_kernel<<<B / 2, 256, SMEM_BYTES>>>(x, out);
}